// round 16
// baseline (speedup 1.0000x reference)
#include <cuda_runtime.h>
#include <cuda_fp16.h>
#include <cstdint>

#define B_   4
#define N_   2048
#define DIN  128
#define H_   4
#define HD_  32
#define LOG2E 1.4426950408889634f

// ---------------- scratch (no allocs allowed) ----------------
__device__ float    g_ei[B_ * N_ * H_];      // pre-scaled by log2e
__device__ float    g_ej[B_ * N_ * H_];
__device__ unsigned g_adjw[(N_ / 32) * N_];  // [jw][i]  transposed bitmask
__device__ __align__(16) unsigned short g_hp[B_ * H_ * HD_ * N_];   // h f16 [b][h][d][j]
__device__ __align__(16) unsigned short g_w16hi[DIN * DIN];         // W split f16
__device__ __align__(16) unsigned short g_w16lo[DIN * DIN];

__device__ __forceinline__ float ex2f(float x) {
    float r; asm("ex2.approx.ftz.f32 %0, %1;" : "=f"(r) : "f"(x)); return r;
}
__device__ __forceinline__ unsigned pk_f16x2(float f0, float f1) {
    unsigned r;
    asm("cvt.rn.f16x2.f32 %0, %1, %2;" : "=r"(r) : "f"(f1), "f"(f0));
    return r;
}
__device__ __forceinline__ void unpk_f16x2(unsigned u, float& f0, float& f1) {
    asm("{ .reg .f16 l, h; mov.b32 {l, h}, %2; cvt.f32.f16 %0, l; cvt.f32.f16 %1, h; }"
        : "=f"(f0), "=f"(f1) : "r"(u));
}
__device__ __forceinline__ unsigned smem_u32(const void* p) {
    unsigned a;
    asm("{ .reg .u64 t; cvta.to.shared.u64 t, %1; cvt.u32.u64 %0, t; }" : "=r"(a) : "l"(p));
    return a;
}
#define CP16(dst, src) asm volatile("cp.async.cg.shared.global [%0], [%1], 16;" :: "r"(dst), "l"(src) : "memory")
#define CP4(dst, src)  asm volatile("cp.async.ca.shared.global [%0], [%1], 4;"  :: "r"(dst), "l"(src) : "memory")

__device__ __forceinline__ void ldsm_x4(unsigned addr, unsigned& a0, unsigned& a1,
                                        unsigned& a2, unsigned& a3) {
    asm volatile("ldmatrix.sync.aligned.m8n8.x4.shared.b16 {%0,%1,%2,%3}, [%4];"
                 : "=r"(a0), "=r"(a1), "=r"(a2), "=r"(a3) : "r"(addr));
}
__device__ __forceinline__ void mma16816(float* d, const unsigned* a, unsigned b0, unsigned b1) {
    asm volatile("mma.sync.aligned.m16n8k16.row.col.f32.f16.f16.f32 "
                 "{%0,%1,%2,%3}, {%4,%5,%6,%7}, {%8,%9}, {%0,%1,%2,%3};"
                 : "+f"(d[0]), "+f"(d[1]), "+f"(d[2]), "+f"(d[3])
                 : "r"(a[0]), "r"(a[1]), "r"(a[2]), "r"(a[3]), "r"(b0), "r"(b1));
}

// ---------------- kernel 0: split W -> f16 hi/lo planes ----------------
__global__ void k_prep(const float* __restrict__ W) {
    const int idx = (blockIdx.x * 256 + threadIdx.x) * 8;
    float4 v0 = *(const float4*)&W[idx];
    float4 v1 = *(const float4*)&W[idx + 4];
    float f[8] = {v0.x, v0.y, v0.z, v0.w, v1.x, v1.y, v1.z, v1.w};
    unsigned hi[4], lo[4];
    #pragma unroll
    for (int p = 0; p < 4; p++) {
        unsigned uh = pk_f16x2(f[2*p], f[2*p+1]);
        float g0, g1; unpk_f16x2(uh, g0, g1);
        hi[p] = uh;
        lo[p] = pk_f16x2(f[2*p] - g0, f[2*p+1] - g1);
    }
    *(uint4*)&g_w16hi[idx] = make_uint4(hi[0], hi[1], hi[2], hi[3]);
    *(uint4*)&g_w16lo[idx] = make_uint4(lo[0], lo[1], lo[2], lo[3]);
}

// ---------------- kernel 1: h = x@W^T via split-f16 HMMA; 32 rows/CTA ----------------
#define GX_HI 0
#define GX_LO 8704
#define GW_HI 17408
#define GW_LO 52224
#define GEMM_SMEM 87040
__global__ void __launch_bounds__(256, 2) k_gemm(const float* __restrict__ x,
                                                 const float* __restrict__ a) {
    extern __shared__ char smg[];
    const unsigned sb = smem_u32(smg);
    const int t = threadIdx.x, wid = t >> 5, lane = t & 31;
    const int row0 = blockIdx.x * 32;

    #pragma unroll
    for (int r = 0; r < 8; r++) {
        int id = t + r * 256;
        int d = id >> 4, q = id & 15;
        CP16(sb + GW_HI + d * 272 + q * 16, &g_w16hi[d * 128 + q * 8]);
        CP16(sb + GW_LO + d * 272 + q * 16, &g_w16lo[d * 128 + q * 8]);
    }
    asm volatile("cp.async.commit_group;" ::: "memory");

    {
        const int row = t >> 3, cq = (t & 7) * 16;
        const float* src = &x[(size_t)(row0 + row) * 128 + cq];
        float f[16];
        #pragma unroll
        for (int p = 0; p < 4; p++) {
            float4 v = *(const float4*)&src[p * 4];
            f[4*p] = v.x; f[4*p+1] = v.y; f[4*p+2] = v.z; f[4*p+3] = v.w;
        }
        unsigned hi[8], lo[8];
        #pragma unroll
        for (int p = 0; p < 8; p++) {
            unsigned uh = pk_f16x2(f[2*p], f[2*p+1]);
            float g0, g1; unpk_f16x2(uh, g0, g1);
            hi[p] = uh;
            lo[p] = pk_f16x2(f[2*p] - g0, f[2*p+1] - g1);
        }
        char* dh = smg + GX_HI + row * 272 + cq * 2;
        char* dl = smg + GX_LO + row * 272 + cq * 2;
        *(uint4*)dh       = make_uint4(hi[0], hi[1], hi[2], hi[3]);
        *(uint4*)(dh+16)  = make_uint4(hi[4], hi[5], hi[6], hi[7]);
        *(uint4*)dl       = make_uint4(lo[0], lo[1], lo[2], lo[3]);
        *(uint4*)(dl+16)  = make_uint4(lo[4], lo[5], lo[6], lo[7]);
    }
    asm volatile("cp.async.wait_group 0;" ::: "memory");
    __syncthreads();

    const int n0 = wid * 16;
    const unsigned aAh0 = sb + GX_HI + (unsigned)(lane & 15) * 272u + ((lane >> 4) & 1) * 16u;
    const unsigned aAh1 = aAh0 + 16u * 272u;
    const unsigned aAl0 = aAh0 + (GX_LO - GX_HI);
    const unsigned aAl1 = aAh1 + (GX_LO - GX_HI);
    const unsigned bB   = sb + GW_HI + (unsigned)(n0 + (lane & 7) + ((lane >> 4) & 1) * 8) * 272u
                        + ((lane >> 3) & 1) * 16u;
    const unsigned bBl  = bB + (GW_LO - GW_HI);

    float acc[2][2][4];
    #pragma unroll
    for (int mt = 0; mt < 2; mt++)
        #pragma unroll
        for (int nt = 0; nt < 2; nt++)
            #pragma unroll
            for (int k = 0; k < 4; k++) acc[mt][nt][k] = 0.f;

    #pragma unroll
    for (int ks = 0; ks < 8; ks++) {
        const unsigned off = (unsigned)ks * 32u;
        unsigned ah0[4], ah1[4], al0[4], al1[4];
        unsigned bh0, bh1, ch0, ch1, bl0, bl1, cl0, cl1;
        ldsm_x4(aAh0 + off, ah0[0], ah0[1], ah0[2], ah0[3]);
        ldsm_x4(aAh1 + off, ah1[0], ah1[1], ah1[2], ah1[3]);
        ldsm_x4(aAl0 + off, al0[0], al0[1], al0[2], al0[3]);
        ldsm_x4(aAl1 + off, al1[0], al1[1], al1[2], al1[3]);
        ldsm_x4(bB  + off, bh0, bh1, ch0, ch1);
        ldsm_x4(bBl + off, bl0, bl1, cl0, cl1);
        mma16816(acc[0][0], ah0, bh0, bh1);
        mma16816(acc[0][0], ah0, bl0, bl1);
        mma16816(acc[0][0], al0, bh0, bh1);
        mma16816(acc[0][1], ah0, ch0, ch1);
        mma16816(acc[0][1], ah0, cl0, cl1);
        mma16816(acc[0][1], al0, ch0, ch1);
        mma16816(acc[1][0], ah1, bh0, bh1);
        mma16816(acc[1][0], ah1, bl0, bl1);
        mma16816(acc[1][0], al1, bh0, bh1);
        mma16816(acc[1][1], ah1, ch0, ch1);
        mma16816(acc[1][1], ah1, cl0, cl1);
        mma16816(acc[1][1], al1, ch0, ch1);
    }

    __syncthreads();
    float* sm32 = (float*)smg;
    #pragma unroll
    for (int mt = 0; mt < 2; mt++)
        #pragma unroll
        for (int nt = 0; nt < 2; nt++) {
            const int r = mt * 16 + (lane >> 2);
            const int c = n0 + nt * 8 + 2 * (lane & 3);
            *(float2*)&sm32[r * 136 + c]       = make_float2(acc[mt][nt][0], acc[mt][nt][1]);
            *(float2*)&sm32[(r + 8) * 136 + c] = make_float2(acc[mt][nt][2], acc[mt][nt][3]);
        }
    __syncthreads();

    {
        const int bb = row0 >> 11, j0l = row0 & 2047;
        const int d = t >> 1, jh = t & 1;
        unsigned u[8];
        #pragma unroll
        for (int p = 0; p < 8; p++)
            u[p] = pk_f16x2(sm32[(jh * 16 + 2*p) * 136 + d], sm32[(jh * 16 + 2*p + 1) * 136 + d]);
        unsigned short* dst = &g_hp[(((size_t)bb * H_ + (d >> 5)) * HD_ + (d & 31)) * N_ + j0l + jh * 16];
        *(uint4*)dst      = make_uint4(u[0], u[1], u[2], u[3]);
        *(uint4*)(dst+8)  = make_uint4(u[4], u[5], u[6], u[7]);
    }

    {
        const int r = t >> 3, q = t & 7;
        const int head = q >> 1, part = q & 1;
        const float* hrow = &sm32[r * 136 + head * 32 + part * 16];
        const float* a1 = &a[head * 64 + part * 16];
        const float* a2 = a1 + 32;
        float p1 = 0.f, p2 = 0.f;
        #pragma unroll
        for (int dd = 0; dd < 16; dd++) {
            float hv = hrow[dd];
            p1 = fmaf(hv, a1[dd], p1);
            p2 = fmaf(hv, a2[dd], p2);
        }
        p1 += __shfl_xor_sync(0xffffffffu, p1, 1);
        p2 += __shfl_xor_sync(0xffffffffu, p2, 1);
        if (part == 0) {
            const int row = row0 + r;
            g_ei[row * H_ + head] = p1 * LOG2E;
            g_ej[row * H_ + head] = p2 * LOG2E;
        }
    }
}

// ---------------- kernel 2: pack adj (8 rows/warp, 2x uint4 out) ----------------
__global__ void k_pack(const int* __restrict__ adj) {
    const int wid = threadIdx.x >> 5, lane = threadIdx.x & 31;
    const int gw = blockIdx.x * 8 + wid;
    const int ip = gw >> 4, w4 = gw & 15;
    const int sub = lane >> 3, idx = lane & 7;
    const size_t base = (size_t)(8 * ip) * N_ + w4 * 128 + sub * 32 + idx * 4;
    unsigned aa[8];
    #pragma unroll
    for (int k = 0; k < 8; k++) {
        int4 v = *(const int4*)&adj[base + (size_t)k * N_];
        aa[k] = ((v.x != 0 ? 1u : 0u) | (v.y != 0 ? 2u : 0u)
               | (v.z != 0 ? 4u : 0u) | (v.w != 0 ? 8u : 0u)) << (idx * 4);
    }
    #pragma unroll
    for (int o = 1; o < 8; o <<= 1)
        #pragma unroll
        for (int k = 0; k < 8; k++)
            aa[k] |= __shfl_xor_sync(0xffffffffu, aa[k], o, 8);
    if (idx == 0) {
        *(uint4*)&g_adjw[(w4 * 4 + sub) * N_ + 8 * ip]     = make_uint4(aa[0], aa[1], aa[2], aa[3]);
        *(uint4*)&g_adjw[(w4 * 4 + sub) * N_ + 8 * ip + 4] = make_uint4(aa[4], aa[5], aa[6], aa[7]);
    }
}

// ---------------- kernel 3: fused scores-in-registers + HMMA; Z via ones-MMA ----------------
#define OFF_H0   0          // 32 x 272
#define OFF_H1   8704
#define OFF_EJ   17408      // 2 x 512B
#define OFF_ADJ  18432      // 2 x 1024B
#define ATTN_SMEM 20480
#define ONES_F16X2 0x3C003C00u

__global__ void __launch_bounds__(128, 4) k_attn(float* __restrict__ out) {
    extern __shared__ char smc[];
    const unsigned sb = smem_u32(smc);
    const int t = threadIdx.x, wid = t >> 5, lane = t & 31;
    const int i0 = blockIdx.x * 64, hh = blockIdx.y, b = blockIdx.z;

    const int r0 = wid * 16 + (lane >> 2);     // local row (and r0+8)
    const float ei0 = g_ei[(b * N_ + i0 + r0) * H_ + hh];
    const float ei1 = g_ei[(b * N_ + i0 + r0 + 8) * H_ + hh];
    const unsigned short* hp = g_hp + ((size_t)((b * H_ + hh) * HD_)) * N_;

    const unsigned bRow = (unsigned)((lane & 7) + ((lane >> 4) & 1) * 8) * 272u
                        + ((lane >> 3) & 1) * 16u;
    const int c0 = 2 * (lane & 3);

    float dacc[4][4];
    #pragma unroll
    for (int nb = 0; nb < 4; nb++)
        #pragma unroll
        for (int k = 0; k < 4; k++) dacc[nb][k] = 0.f;
    float zacc[4] = {0.f, 0.f, 0.f, 0.f};      // Z via ones-B MMA

    #define ISSUE_COPIES(tl, buf)                                                       \
    do {                                                                                \
        const int jj0 = (tl) * 128;                                                     \
        const unsigned offH_ = (buf) ? OFF_H1 : OFF_H0;                                 \
        _Pragma("unroll")                                                               \
        for (int r = 0; r < 4; r++) {                                                   \
            int id = t + r * 128;                                                       \
            int d = id >> 4, q = id & 15;                                               \
            CP16(sb + offH_ + d * 272 + q * 16, &hp[(size_t)d * N_ + jj0 + q * 8]);     \
        }                                                                               \
        CP4(sb + OFF_EJ + (buf) * 512 + t * 4, &g_ej[(b * N_ + jj0 + t) * H_ + hh]);    \
        if (t < 64) {                                                                   \
            int jwl = t >> 4, il4 = (t & 15) * 4;                                       \
            CP16(sb + OFF_ADJ + (buf) * 1024 + (jwl * 64 + il4) * 4,                    \
                 &g_adjw[((jj0 >> 5) + jwl) * N_ + i0 + il4]);                          \
        }                                                                               \
        asm volatile("cp.async.commit_group;" ::: "memory");                            \
    } while (0)

    ISSUE_COPIES(0, 0);

    for (int tile = 0; tile < 16; tile++) {
        const int cur = tile & 1;

        __syncthreads();
        if (tile + 1 < 16) {
            ISSUE_COPIES(tile + 1, cur ^ 1);
            asm volatile("cp.async.wait_group 1;" ::: "memory");
        } else {
            asm volatile("cp.async.wait_group 0;" ::: "memory");
        }
        __syncthreads();

        const unsigned* aw = (const unsigned*)(smc + OFF_ADJ + cur * 1024);
        unsigned wr0[4], wr1[4];
        #pragma unroll
        for (int jw = 0; jw < 4; jw++) {
            wr0[jw] = aw[jw * 64 + r0];
            wr1[jw] = aw[jw * 64 + r0 + 8];
        }
        const float* ejs = (const float*)(smc + OFF_EJ + cur * 512);
        const unsigned aB0 = sb + (cur ? OFF_H1 : OFF_H0) + bRow;
        const unsigned aB1 = aB0 + 16u * 272u;

        #pragma unroll
        for (int ks = 0; ks < 8; ks++) {
            const float* ejk = ejs + ks * 16;
            float2 eA = *(const float2*)&ejk[c0];
            float2 eB = *(const float2*)&ejk[c0 + 8];
            const unsigned wa = wr0[ks >> 1] >> ((ks & 1) * 16 + c0);
            const unsigned wb = wr1[ks >> 1] >> ((ks & 1) * 16 + c0);

            float s;
            s = ei0 + eA.x; s = fmaxf(s, 0.2f * s); float e00 = ex2f(s);
            s = ei0 + eA.y; s = fmaxf(s, 0.2f * s); float e01 = ex2f(s);
            s = ei0 + eB.x; s = fmaxf(s, 0.2f * s); float e08 = ex2f(s);
            s = ei0 + eB.y; s = fmaxf(s, 0.2f * s); float e09 = ex2f(s);
            s = ei1 + eA.x; s = fmaxf(s, 0.2f * s); float e10 = ex2f(s);
            s = ei1 + eA.y; s = fmaxf(s, 0.2f * s); float e11 = ex2f(s);
            s = ei1 + eB.x; s = fmaxf(s, 0.2f * s); float e18 = ex2f(s);
            s = ei1 + eB.y; s = fmaxf(s, 0.2f * s); float e19 = ex2f(s);

            // mask in f16 domain: 2 bits -> one 32-bit AND mask per pair
            const unsigned maskA0 = ((wa & 1u)   ? 0x0000FFFFu : 0u) | ((wa & 2u)   ? 0xFFFF0000u : 0u);
            const unsigned maskA8 = ((wa & 256u) ? 0x0000FFFFu : 0u) | ((wa & 512u) ? 0xFFFF0000u : 0u);
            const unsigned maskB0 = ((wb & 1u)   ? 0x0000FFFFu : 0u) | ((wb & 2u)   ? 0xFFFF0000u : 0u);
            const unsigned maskB8 = ((wb & 256u) ? 0x0000FFFFu : 0u) | ((wb & 512u) ? 0xFFFF0000u : 0u);

            unsigned afrag[4];
            afrag[0] = pk_f16x2(e00, e01) & maskA0;
            afrag[1] = pk_f16x2(e10, e11) & maskB0;
            afrag[2] = pk_f16x2(e08, e09) & maskA8;
            afrag[3] = pk_f16x2(e18, e19) & maskB8;

            const unsigned off = (unsigned)ks * 32u;
            unsigned b0, b1, c0r, c1r, f0, f1, g0, g1;
            ldsm_x4(aB0 + off, b0, b1, c0r, c1r);
            ldsm_x4(aB1 + off, f0, f1, g0, g1);
            mma16816(dacc[0], afrag, b0, b1);
            mma16816(dacc[1], afrag, c0r, c1r);
            mma16816(dacc[2], afrag, f0, f1);
            mma16816(dacc[3], afrag, g0, g1);
            mma16816(zacc, afrag, ONES_F16X2, ONES_F16X2);   // Z row-sums, free on tensor pipe
        }
    }

    // Z comes directly from ones-MMA (all n-columns equal) — no shuffle reduce
    const float zi0 = 1.0f / zacc[0], zi1 = 1.0f / zacc[2];

    const size_t row_g = (size_t)(b * N_) + i0 + r0;
    float* o0 = out + row_g * DIN + hh * HD_ + c0;
    float* o1 = o0 + 8 * DIN;
    #pragma unroll
    for (int nb = 0; nb < 4; nb++) {
        *(float2*)(o0 + nb * 8) = make_float2(dacc[nb][0] * zi0, dacc[nb][1] * zi0);
        *(float2*)(o1 + nb * 8) = make_float2(dacc[nb][2] * zi1, dacc[nb][3] * zi1);
    }
}

// ---------------- launch ----------------
extern "C" void kernel_launch(void* const* d_in, const int* in_sizes, int n_in,
                              void* d_out, int out_size) {
    const float* x   = (const float*)d_in[0];
    const int*   adj = (const int*)d_in[1];
    const float* W   = (const float*)d_in[2];
    const float* a   = (const float*)d_in[3];
    float*       out = (float*)d_out;

    cudaFuncSetAttribute(k_gemm, cudaFuncAttributeMaxDynamicSharedMemorySize, GEMM_SMEM);
    cudaFuncSetAttribute(k_attn, cudaFuncAttributeMaxDynamicSharedMemorySize, ATTN_SMEM);

    k_prep<<<8, 256>>>(W);
    k_gemm<<<B_ * N_ / 32, 256, GEMM_SMEM>>>(x, a);
    k_pack<<<512, 256>>>(adj);
    k_attn<<<dim3(N_ / 64, H_, B_), 128, ATTN_SMEM>>>(out);
}